// round 7
// baseline (speedup 1.0000x reference)
#include <cuda_runtime.h>
#include <math.h>

#define BB  8
#define NPT 2048
#define NTOT (BB*NPT)
#define HID 256
#define NITER 14

typedef unsigned long long u64;

// ---------------- f32x2 packed helpers (sm_103a) ----------------
__device__ __forceinline__ u64 pk2(float lo, float hi) {
    u64 r; asm("mov.b64 %0,{%1,%2};" : "=l"(r) : "f"(lo), "f"(hi)); return r;
}
__device__ __forceinline__ void up2(u64 v, float& lo, float& hi) {
    asm("mov.b64 {%0,%1},%2;" : "=f"(lo), "=f"(hi) : "l"(v));
}
__device__ __forceinline__ u64 fma2_(u64 a, u64 b, u64 c) {
    u64 r; asm("fma.rn.f32x2 %0,%1,%2,%3;" : "=l"(r) : "l"(a), "l"(b), "l"(c)); return r;
}
__device__ __forceinline__ float ex2_(float x) {
    float r; asm("ex2.approx.f32 %0,%1;" : "=f"(r) : "f"(x)); return r;
}

// ---------------- persistent scratch ----------------
__device__ float4 g_xp[NTOT];   // noise points packed: (x,y,z,|x|^2)
__device__ float4 g_yp[NTOT];   // x0 points packed:    (x,y,z,|y|^2)
// deinterleaved coords (SoA) for the reduce-side of k_half
__device__ __align__(16) float g_xx[NTOT], g_xy[NTOT], g_xz[NTOT];
__device__ __align__(16) float g_yx[NTOT], g_yy[NTOT], g_yz[NTOT];
// folded column constants: cX = f - 0.5|x|^2, cY = g - 0.5|y|^2
__device__ __align__(16) float g_cX[NTOT], g_cY[NTOT];
__device__ float  g_g[NTOT];
__device__ float  g_std[BB];
__device__ int    g_idx[NTOT];

// ---------------- per-batch std (ddof=1) ----------------
__global__ void k_std(const float* __restrict__ cloud) {
    __shared__ float red[256];
    const int b = blockIdx.x;
    const float* p = cloud + b * NPT * 3;
    const int tid = threadIdx.x;
    float s = 0.f;
    for (int i = tid; i < NPT * 3; i += 256) s += p[i];
    red[tid] = s; __syncthreads();
    for (int o = 128; o > 0; o >>= 1) { if (tid < o) red[tid] += red[tid + o]; __syncthreads(); }
    const float mean = red[0] / (float)(NPT * 3);
    __syncthreads();
    float s2 = 0.f;
    for (int i = tid; i < NPT * 3; i += 256) { float d = p[i] - mean; s2 = fmaf(d, d, s2); }
    red[tid] = s2; __syncthreads();
    for (int o = 128; o > 0; o >>= 1) { if (tid < o) red[tid] += red[tid + o]; __syncthreads(); }
    if (tid == 0) g_std[b] = sqrtf(red[0] / (float)(NPT * 3 - 1));
}

// ---------------- pack points, deinterleave, init folded constants ----------------
__global__ void k_pack(const float* __restrict__ cloud, const float* __restrict__ noise) {
    int i = blockIdx.x * blockDim.x + threadIdx.x;
    if (i >= NTOT) return;
    int b = i >> 11;
    float sd = g_std[b];
    float c0 = cloud[i * 3 + 0] / sd;
    float c1 = cloud[i * 3 + 1] / sd;
    float c2 = cloud[i * 3 + 2] / sd;
    float yn = __fadd_rn(__fadd_rn(__fmul_rn(c0, c0), __fmul_rn(c1, c1)), __fmul_rn(c2, c2));
    g_yp[i] = make_float4(c0, c1, c2, yn);
    g_yx[i] = c0; g_yy[i] = c1; g_yz[i] = c2;
    float n0 = noise[i * 3 + 0], n1 = noise[i * 3 + 1], n2 = noise[i * 3 + 2];
    float xn = __fadd_rn(__fadd_rn(__fmul_rn(n0, n0), __fmul_rn(n1, n1)), __fmul_rn(n2, n2));
    g_xp[i] = make_float4(n0, n1, n2, xn);
    g_xx[i] = n0; g_xy[i] = n1; g_xz[i] = n2;
    // phi == 0 initially  ->  c = -0.5*|p|^2
    g_cX[i] = __fmul_rn(-0.5f, xn);
    g_cY[i] = __fmul_rn(-0.5f, yn);
}

// log2(1/2048) is exactly -11
#define LOGC2 (-11.0f)
#define LN2F  (0.6931471805599453f)
#define SKIP_LOG2 30.0f

// ---------------- one Sinkhorn half-update: single-pass online LSE + vote-skip ----------------
// t_raw(i,j) = q_i . p_j + c_j   (c_j = phi_j - 0.5|p_j|^2; row term -0.5|q_i|^2
// is max-invariant and cancels in (t - m): applied only in the epilogue)
// DIR==0: q = noise(x), p = x0(y), c = cY -> writes cX (= f - 0.5|x|^2)
// DIR==1: q = x0(y),   p = noise(x), c = cX -> writes g and cY
template <int DIR>
__global__ void __launch_bounds__(256) k_half(float eps, float ie2 /* (1/eps)*log2(e) */) {
    __shared__ __align__(16) float sX[NPT], sY[NPT], sZ[NPT], sC[NPT];
    const int b = blockIdx.y;
    const int base = b * NPT;
    const float* __restrict__ PXs = DIR ? g_xx : g_yx;
    const float* __restrict__ PYs = DIR ? g_xy : g_yy;
    const float* __restrict__ PZs = DIR ? g_xz : g_yz;
    const float* __restrict__ PCs = DIR ? g_cX : g_cY;
    const float4* __restrict__ Pq = DIR ? g_yp : g_xp;

    const int tid = threadIdx.x;
    {
        const float4* vx = (const float4*)(PXs + base);
        const float4* vy = (const float4*)(PYs + base);
        const float4* vz = (const float4*)(PZs + base);
        const float4* vc = (const float4*)(PCs + base);
        float4* dx = (float4*)sX; float4* dy = (float4*)sY;
        float4* dz = (float4*)sZ; float4* dc = (float4*)sC;
#pragma unroll
        for (int j = tid; j < NPT / 4; j += 256) {
            dx[j] = vx[j]; dy[j] = vy[j]; dz[j] = vz[j]; dc[j] = vc[j];
        }
    }
    __syncthreads();

    const u64* __restrict__ X = (const u64*)sX;
    const u64* __restrict__ Y = (const u64*)sY;
    const u64* __restrict__ Z = (const u64*)sZ;
    const u64* __restrict__ C = (const u64*)sC;

    const int warp = tid >> 5, lane = tid & 31;
    const int r0 = blockIdx.x * 32 + warp * 4;

    u64 qx2[4], qy2[4], qz2[4];
    float qw[4];
#pragma unroll
    for (int k = 0; k < 4; k++) {
        float4 q = Pq[base + r0 + k];
        qx2[k] = pk2(q.x, q.x);
        qy2[k] = pk2(q.y, q.y);
        qz2[k] = pk2(q.z, q.z);
        qw[k] = q.w;
    }

    const u64 IE2P = pk2(ie2, ie2);
    const float D = SKIP_LOG2 / ie2;           // skip margin in t-units

    float m[4]   = {-INFINITY, -INFINITY, -INFINITY, -INFINITY};
    float acc[4] = {0.f, 0.f, 0.f, 0.f};
    u64   K[4]   = {0, 0, 0, 0};               // defined before first use (iter 0 updates all)
    float thrmin = -INFINITY;

#pragma unroll 2
    for (int it = 0; it < NPT / 64; ++it) {
        const int jj = lane + it * 32;
        const u64 px = X[jj], py = Y[jj], pz = Z[jj], pc = C[jj];
        u64 t0 = fma2_(qz2[0], pz, fma2_(qy2[0], py, fma2_(qx2[0], px, pc)));
        u64 t1 = fma2_(qz2[1], pz, fma2_(qy2[1], py, fma2_(qx2[1], px, pc)));
        u64 t2 = fma2_(qz2[2], pz, fma2_(qy2[2], py, fma2_(qx2[2], px, pc)));
        u64 t3 = fma2_(qz2[3], pz, fma2_(qy2[3], py, fma2_(qx2[3], px, pc)));
        float l0, h0, l1, h1, l2, h2, l3, h3;
        up2(t0, l0, h0); up2(t1, l1, h1); up2(t2, l2, h2); up2(t3, l3, h3);
        float mx0 = fmaxf(l0, h0), mx1 = fmaxf(l1, h1);
        float mx2 = fmaxf(l2, h2), mx3 = fmaxf(l3, h3);
        float amax = fmaxf(fmaxf(mx0, mx1), fmaxf(mx2, mx3));

        if (__any_sync(0xffffffffu, amax > thrmin)) {
            bool upd = false;
            if (mx0 > m[0]) { acc[0] = __fmul_rn(acc[0], ex2_(__fmul_rn(__fadd_rn(m[0], -mx0), ie2)));
                              m[0] = mx0; K[0] = pk2(-__fmul_rn(mx0, ie2), -__fmul_rn(mx0, ie2)); upd = true; }
            if (mx1 > m[1]) { acc[1] = __fmul_rn(acc[1], ex2_(__fmul_rn(__fadd_rn(m[1], -mx1), ie2)));
                              m[1] = mx1; K[1] = pk2(-__fmul_rn(mx1, ie2), -__fmul_rn(mx1, ie2)); upd = true; }
            if (mx2 > m[2]) { acc[2] = __fmul_rn(acc[2], ex2_(__fmul_rn(__fadd_rn(m[2], -mx2), ie2)));
                              m[2] = mx2; K[2] = pk2(-__fmul_rn(mx2, ie2), -__fmul_rn(mx2, ie2)); upd = true; }
            if (mx3 > m[3]) { acc[3] = __fmul_rn(acc[3], ex2_(__fmul_rn(__fadd_rn(m[3], -mx3), ie2)));
                              m[3] = mx3; K[3] = pk2(-__fmul_rn(mx3, ie2), -__fmul_rn(mx3, ie2)); upd = true; }
            if (upd) thrmin = __fadd_rn(fminf(fminf(m[0], m[1]), fminf(m[2], m[3])), -D);

            u64 ea0 = fma2_(IE2P, t0, K[0]);
            u64 ea1 = fma2_(IE2P, t1, K[1]);
            u64 ea2 = fma2_(IE2P, t2, K[2]);
            u64 ea3 = fma2_(IE2P, t3, K[3]);
            float e0l, e0h, e1l, e1h, e2l, e2h, e3l, e3h;
            up2(ea0, e0l, e0h); up2(ea1, e1l, e1h); up2(ea2, e2l, e2h); up2(ea3, e3l, e3h);
            acc[0] = __fadd_rn(__fadd_rn(acc[0], ex2_(e0l)), ex2_(e0h));
            acc[1] = __fadd_rn(__fadd_rn(acc[1], ex2_(e1l)), ex2_(e1h));
            acc[2] = __fadd_rn(__fadd_rn(acc[2], ex2_(e2l)), ex2_(e2h));
            acc[3] = __fadd_rn(__fadd_rn(acc[3], ex2_(e3l)), ex2_(e3h));
        }
    }

    // ---- epilogue: cross-lane combine (max-reduce, rescale, sum-reduce)
    float mw[4], sw[4];
#pragma unroll
    for (int k = 0; k < 4; k++) {
        float mm = m[k];
#pragma unroll
        for (int o = 16; o; o >>= 1) mm = fmaxf(mm, __shfl_xor_sync(0xffffffffu, mm, o));
        mw[k] = mm;
        float a = __fmul_rn(acc[k], ex2_(__fmul_rn(__fadd_rn(m[k], -mm), ie2)));
#pragma unroll
        for (int o = 16; o; o >>= 1) a += __shfl_xor_sync(0xffffffffu, a, o);
        sw[k] = a;
    }

    if (lane == 0) {
#pragma unroll
        for (int k = 0; k < 4; k++) {
            // m_full = m_raw - 0.5|q|^2 ; m2 = m_full*ie2 + LOGC2
            float mfull = fmaf(-0.5f, qw[k], mw[k]);
            float m2 = fmaf(mfull, ie2, LOGC2);
            float res = __fmul_rn(-eps, fmaf(m2, LN2F, logf(sw[k])));
            const int i = base + r0 + k;
            if (DIR == 0) {
                g_cX[i] = fmaf(-0.5f, qw[k], res);     // f - 0.5|x|^2 for next half
            } else {
                g_g[i]  = res;                          // needed by argmin
                g_cY[i] = fmaf(-0.5f, qw[k], res);     // g - 0.5|y|^2 for next iter
            }
        }
    }
}

// ---------------- argmin over m of (sqdist - g_m), first-index ties ----------------
__global__ void __launch_bounds__(256) k_argmin() {
    __shared__ float4 sp[NPT];
    __shared__ float  sg[NPT];
    const int b = blockIdx.y;
    const int base = b * NPT;
    const int tid = threadIdx.x;
    for (int j = tid; j < NPT; j += 256) { sp[j] = g_yp[base + j]; sg[j] = g_g[base + j]; }
    __syncthreads();
    const int warp = tid >> 5, lane = tid & 31;
    const int r0 = blockIdx.x * 32 + warp * 4;

    float qx[4], qy[4], qz[4], qn[4];
#pragma unroll
    for (int k = 0; k < 4; k++) {
        float4 q = g_xp[base + r0 + k];
        qx[k] = q.x; qy[k] = q.y; qz[k] = q.z; qn[k] = q.w;
    }
    float bv[4] = {INFINITY, INFINITY, INFINITY, INFINITY};
    int   bi[4] = {0, 0, 0, 0};
#pragma unroll 2
    for (int j = lane; j < NPT; j += 32) {
        const float4 p = sp[j];
        const float gg = sg[j];
#pragma unroll
        for (int k = 0; k < 4; k++) {
            float d = fmaf(qz[k], p.z, fmaf(qy[k], p.y, __fmul_rn(qx[k], p.x)));
            float s = fmaf(-2.f, d, __fadd_rn(qn[k], p.w));
            s = fmaxf(s, 0.f);
            float v = __fadd_rn(s, -gg);
            if (v < bv[k]) { bv[k] = v; bi[k] = j; }
        }
    }
#pragma unroll
    for (int k = 0; k < 4; k++) {
#pragma unroll
        for (int o = 16; o; o >>= 1) {
            float v2 = __shfl_xor_sync(0xffffffffu, bv[k], o);
            int   i2 = __shfl_xor_sync(0xffffffffu, bi[k], o);
            if (v2 < bv[k] || (v2 == bv[k] && i2 < bi[k])) { bv[k] = v2; bi[k] = i2; }
        }
    }
    if (lane == 0) {
#pragma unroll
        for (int k = 0; k < 4; k++) g_idx[base + r0 + k] = bi[k];
    }
}

// ---------------- gather + MLP head, write (v_pred, v) ----------------
__global__ void __launch_bounds__(256) k_mlp(const float* __restrict__ noise, const float* __restrict__ tt,
                                             const float* __restrict__ W1, const float* __restrict__ Wt,
                                             const float* __restrict__ b1, const float* __restrict__ W2,
                                             const float* __restrict__ b2, float* __restrict__ out) {
    __shared__ float sW1[3 * HID], sW2[HID * 3], sWt[HID], sb1[HID];
    const int tid = threadIdx.x;
    for (int i = tid; i < 3 * HID; i += 256) { sW1[i] = W1[i]; sW2[i] = W2[i]; }
    for (int i = tid; i < HID; i += 256) { sWt[i] = Wt[i]; sb1[i] = b1[i]; }
    __syncthreads();

    const int p = blockIdx.x * 256 + tid;
    const int b = p >> 11;
    const float t = tt[b];
    const int id = g_idx[p];
    const float4 y = g_yp[(b << 11) + id];
    const float n0 = noise[p * 3 + 0], n1 = noise[p * 3 + 1], n2 = noise[p * 3 + 2];
    const float v0 = __fadd_rn(n0, -y.x);
    const float v1 = __fadd_rn(n1, -y.y);
    const float v2 = __fadd_rn(n2, -y.z);
    const float omt = __fadd_rn(1.f, -t);
    const float x0t = __fadd_rn(__fmul_rn(omt, y.x), __fmul_rn(t, n0));
    const float x1t = __fadd_rn(__fmul_rn(omt, y.y), __fmul_rn(t, n1));
    const float x2t = __fadd_rn(__fmul_rn(omt, y.z), __fmul_rn(t, n2));

    float a0 = b2[0], a1 = b2[1], a2 = b2[2];
#pragma unroll 8
    for (int j = 0; j < HID; j++) {
        float h = fmaf(x2t, sW1[2 * HID + j], fmaf(x1t, sW1[HID + j], __fmul_rn(x0t, sW1[j])));
        h = __fadd_rn(__fadd_rn(h, __fmul_rn(t, sWt[j])), sb1[j]);
        h = fmaxf(h, 0.f);
        a0 = fmaf(h, sW2[j * 3 + 0], a0);
        a1 = fmaf(h, sW2[j * 3 + 1], a1);
        a2 = fmaf(h, sW2[j * 3 + 2], a2);
    }
    out[p * 3 + 0] = a0;
    out[p * 3 + 1] = a1;
    out[p * 3 + 2] = a2;
    out[NTOT * 3 + p * 3 + 0] = v0;
    out[NTOT * 3 + p * 3 + 1] = v1;
    out[NTOT * 3 + p * 3 + 2] = v2;
}

// ---------------- launcher ----------------
extern "C" void kernel_launch(void* const* d_in, const int* in_sizes, int n_in,
                              void* d_out, int out_size) {
    const float* cloud = (const float*)d_in[0];
    const float* noise = (const float*)d_in[1];
    const float* t     = (const float*)d_in[2];
    const float* W1    = (const float*)d_in[3];
    const float* Wt    = (const float*)d_in[4];
    const float* b1    = (const float*)d_in[5];
    const float* W2    = (const float*)d_in[6];
    const float* b2    = (const float*)d_in[7];
    float* out = (float*)d_out;

    k_std<<<BB, 256>>>(cloud);
    k_pack<<<NTOT / 256, 256>>>(cloud, noise);

    // EPS_LIST = np.geomspace(32.0, 0.001**2, 14).astype(np.float32)
    const double blur2 = 0.001 * 0.001;
    const double l0 = log10(32.0);
    const double l1 = log10(blur2);
    const double step = (l1 - l0) / (double)(NITER - 1);
    const double LOG2E = 1.4426950408889634;
    const dim3 grid(NPT / 32, BB);

    for (int it = 0; it < NITER; it++) {
        double ev;
        if (it == 0)              ev = 32.0;
        else if (it == NITER - 1) ev = blur2;
        else                      ev = pow(10.0, l0 + (double)it * step);
        const float eps = (float)ev;
        const float ie2 = (float)((double)(1.0f / eps) * LOG2E);
        k_half<0><<<grid, 256>>>(eps, ie2);  // f-update
        k_half<1><<<grid, 256>>>(eps, ie2);  // g-update
    }

    k_argmin<<<grid, 256>>>();
    k_mlp<<<NTOT / 256, 256>>>(noise, t, W1, Wt, b1, W2, b2, out);

    (void)in_sizes; (void)n_in; (void)out_size;
}

// round 8
// speedup vs baseline: 1.3800x; 1.3800x over previous
#include <cuda_runtime.h>
#include <math.h>

#define BB  8
#define NPT 2048
#define NTOT (BB*NPT)
#define HID 256
#define NITER 14

typedef unsigned long long u64;

// ---------------- f32x2 packed helpers (sm_103a) ----------------
__device__ __forceinline__ u64 pk2(float lo, float hi) {
    u64 r; asm("mov.b64 %0,{%1,%2};" : "=l"(r) : "f"(lo), "f"(hi)); return r;
}
__device__ __forceinline__ void up2(u64 v, float& lo, float& hi) {
    asm("mov.b64 {%0,%1},%2;" : "=f"(lo), "=f"(hi) : "l"(v));
}
__device__ __forceinline__ u64 fma2_(u64 a, u64 b, u64 c) {
    u64 r; asm("fma.rn.f32x2 %0,%1,%2,%3;" : "=l"(r) : "l"(a), "l"(b), "l"(c)); return r;
}
__device__ __forceinline__ float ex2_(float x) {
    float r; asm("ex2.approx.f32 %0,%1;" : "=f"(r) : "f"(x)); return r;
}

// ---------------- persistent scratch ----------------
__device__ float4 g_xp[NTOT];   // noise points packed: (x,y,z,|x|^2)
__device__ float4 g_yp[NTOT];   // x0 points packed:    (x,y,z,|y|^2)
// interleaved pair tiles for k_half reduce side:
//   g_xy*[pair] = (x_{2j}, x_{2j+1}, y_{2j}, y_{2j+1})
//   g_zc*[pair] = (z_{2j}, z_{2j+1}, c_{2j}, c_{2j+1}),  c = phi - 0.5*|p|^2
__device__ float4 g_xyX[NTOT/2], g_zcX[NTOT/2];   // X side (noise)
__device__ float4 g_xyY[NTOT/2], g_zcY[NTOT/2];   // Y side (x0)
__device__ float  g_g[NTOT];
__device__ float  g_std[BB];
__device__ int    g_idx[NTOT];

// ---------------- per-batch std (ddof=1) ----------------
__global__ void k_std(const float* __restrict__ cloud) {
    __shared__ float red[256];
    const int b = blockIdx.x;
    const float* p = cloud + b * NPT * 3;
    const int tid = threadIdx.x;
    float s = 0.f;
    for (int i = tid; i < NPT * 3; i += 256) s += p[i];
    red[tid] = s; __syncthreads();
    for (int o = 128; o > 0; o >>= 1) { if (tid < o) red[tid] += red[tid + o]; __syncthreads(); }
    const float mean = red[0] / (float)(NPT * 3);
    __syncthreads();
    float s2 = 0.f;
    for (int i = tid; i < NPT * 3; i += 256) { float d = p[i] - mean; s2 = fmaf(d, d, s2); }
    red[tid] = s2; __syncthreads();
    for (int o = 128; o > 0; o >>= 1) { if (tid < o) red[tid] += red[tid + o]; __syncthreads(); }
    if (tid == 0) g_std[b] = sqrtf(red[0] / (float)(NPT * 3 - 1));
}

// ---------------- pack points, build interleaved tiles, init folded constants ----------------
__global__ void k_pack(const float* __restrict__ cloud, const float* __restrict__ noise) {
    int i = blockIdx.x * blockDim.x + threadIdx.x;
    if (i >= NTOT) return;
    int b = i >> 11;
    float sd = g_std[b];
    float c0 = cloud[i * 3 + 0] / sd;
    float c1 = cloud[i * 3 + 1] / sd;
    float c2 = cloud[i * 3 + 2] / sd;
    float yn = __fadd_rn(__fadd_rn(__fmul_rn(c0, c0), __fmul_rn(c1, c1)), __fmul_rn(c2, c2));
    g_yp[i] = make_float4(c0, c1, c2, yn);
    float n0 = noise[i * 3 + 0], n1 = noise[i * 3 + 1], n2 = noise[i * 3 + 2];
    float xn = __fadd_rn(__fadd_rn(__fmul_rn(n0, n0), __fmul_rn(n1, n1)), __fmul_rn(n2, n2));
    g_xp[i] = make_float4(n0, n1, n2, xn);

    const int pr = i >> 1, h = i & 1;
    float* fxyX = (float*)g_xyX; float* fzcX = (float*)g_zcX;
    float* fxyY = (float*)g_xyY; float* fzcY = (float*)g_zcY;
    fxyX[pr * 4 + h]     = n0;
    fxyX[pr * 4 + 2 + h] = n1;
    fzcX[pr * 4 + h]     = n2;
    fzcX[pr * 4 + 2 + h] = __fmul_rn(-0.5f, xn);   // phi==0 -> c = -0.5|x|^2
    fxyY[pr * 4 + h]     = c0;
    fxyY[pr * 4 + 2 + h] = c1;
    fzcY[pr * 4 + h]     = c2;
    fzcY[pr * 4 + 2 + h] = __fmul_rn(-0.5f, yn);
}

// log2(1/2048) is exactly -11
#define LOGC2 (-11.0f)
#define LN2F  (0.6931471805599453f)

// ---------------- one Sinkhorn half-update (two-pass, 2 rows/warp, grid 1024) ----------------
// t_raw(i,j) = q_i . p_j + c_j   (c_j = phi_j - 0.5|p_j|^2; row term -0.5|q_i|^2
// is max-invariant and cancels in (t - m): applied only in the epilogue)
// DIR==0: q = noise(x), p = x0(y) -> writes cX; DIR==1: q = x0(y), p = noise(x) -> writes g, cY
template <int DIR>
__global__ void __launch_bounds__(256, 5) k_half(float eps, float ie2 /* (1/eps)*log2(e) */) {
    __shared__ __align__(16) ulonglong2 sXY[NPT/2], sZC[NPT/2];
    const int b = blockIdx.y;
    const int base = b * NPT;
    const float4* __restrict__ vxy = (DIR ? g_xyX : g_xyY) + (base >> 1);
    const float4* __restrict__ vzc = (DIR ? g_zcX : g_zcY) + (base >> 1);
    const float4* __restrict__ Pq  = DIR ? g_yp : g_xp;

    const int tid = threadIdx.x;
    {
        float4* dxy = (float4*)sXY; float4* dzc = (float4*)sZC;
#pragma unroll
        for (int j = tid; j < NPT / 2; j += 256) { dxy[j] = vxy[j]; dzc[j] = vzc[j]; }
    }
    __syncthreads();

    const int warp = tid >> 5, lane = tid & 31;
    const int r0 = blockIdx.x * 16 + warp * 2;

    const float4 q0 = Pq[base + r0];
    const float4 q1 = Pq[base + r0 + 1];
    const u64 qx20 = pk2(q0.x, q0.x), qy20 = pk2(q0.y, q0.y), qz20 = pk2(q0.z, q0.z);
    const u64 qx21 = pk2(q1.x, q1.x), qy21 = pk2(q1.y, q1.y), qz21 = pk2(q1.z, q1.z);

    // ---- pass 1: per-row max of t_raw = q.p + c_j
    float m0l = -INFINITY, m0h = -INFINITY, m1l = -INFINITY, m1h = -INFINITY;
#pragma unroll 4
    for (int it = 0; it < NPT / 64; ++it) {
        const int jj = lane + it * 32;
        const ulonglong2 pxy = sXY[jj];
        const ulonglong2 pzc = sZC[jj];
        u64 t0 = fma2_(qz20, pzc.x, fma2_(qy20, pxy.y, fma2_(qx20, pxy.x, pzc.y)));
        u64 t1 = fma2_(qz21, pzc.x, fma2_(qy21, pxy.y, fma2_(qx21, pxy.x, pzc.y)));
        float l0, h0, l1, h1;
        up2(t0, l0, h0); up2(t1, l1, h1);
        m0l = fmaxf(m0l, l0); m0h = fmaxf(m0h, h0);
        m1l = fmaxf(m1l, l1); m1h = fmaxf(m1h, h1);
    }
    float m0 = fmaxf(m0l, m0h);
    float m1 = fmaxf(m1l, m1h);
#pragma unroll
    for (int o = 16; o; o >>= 1) m0 = fmaxf(m0, __shfl_xor_sync(0xffffffffu, m0, o));
#pragma unroll
    for (int o = 16; o; o >>= 1) m1 = fmaxf(m1, __shfl_xor_sync(0xffffffffu, m1, o));
    const float k0 = -__fmul_rn(m0, ie2);
    const float k1 = -__fmul_rn(m1, ie2);
    const u64 K0 = pk2(k0, k0);
    const u64 K1 = pk2(k1, k1);
    const u64 IE2P = pk2(ie2, ie2);

    // ---- pass 2: sum of exp2((t_raw - m_raw)*ie2)
    float a0l = 0.f, a0h = 0.f, a1l = 0.f, a1h = 0.f;
#pragma unroll 4
    for (int it = 0; it < NPT / 64; ++it) {
        const int jj = lane + it * 32;
        const ulonglong2 pxy = sXY[jj];
        const ulonglong2 pzc = sZC[jj];
        u64 t0 = fma2_(qz20, pzc.x, fma2_(qy20, pxy.y, fma2_(qx20, pxy.x, pzc.y)));
        u64 t1 = fma2_(qz21, pzc.x, fma2_(qy21, pxy.y, fma2_(qx21, pxy.x, pzc.y)));
        u64 ea0 = fma2_(IE2P, t0, K0);
        u64 ea1 = fma2_(IE2P, t1, K1);
        float e0l, e0h, e1l, e1h;
        up2(ea0, e0l, e0h); up2(ea1, e1l, e1h);
        a0l += ex2_(e0l); a0h += ex2_(e0h);
        a1l += ex2_(e1l); a1h += ex2_(e1h);
    }
    float a0 = __fadd_rn(a0l, a0h);
    float a1 = __fadd_rn(a1l, a1h);
#pragma unroll
    for (int o = 16; o; o >>= 1) a0 += __shfl_xor_sync(0xffffffffu, a0, o);
#pragma unroll
    for (int o = 16; o; o >>= 1) a1 += __shfl_xor_sync(0xffffffffu, a1, o);

    if (lane == 0) {
        const int pr4 = ((base + r0) >> 1) * 4;   // pair slot (r0 even: both rows share it)
        float mm[2] = {m0, m1};
        float aa[2] = {a0, a1};
        float qww[2] = {q0.w, q1.w};
#pragma unroll
        for (int k = 0; k < 2; k++) {
            // m_full = m_raw - 0.5|q|^2 ; m2 = m_full*ie2 + LOGC2
            float mfull = fmaf(-0.5f, qww[k], mm[k]);
            float m2 = fmaf(mfull, ie2, LOGC2);
            float res = __fmul_rn(-eps, fmaf(m2, LN2F, logf(aa[k])));
            float cnew = fmaf(-0.5f, qww[k], res);
            if (DIR == 0) {
                ((float*)g_zcX)[pr4 + 2 + k] = cnew;   // f - 0.5|x|^2 for next half
            } else {
                g_g[base + r0 + k] = res;               // needed by argmin
                ((float*)g_zcY)[pr4 + 2 + k] = cnew;   // g - 0.5|y|^2 for next iter
            }
        }
    }
}

// ---------------- argmin over m of (sqdist - g_m), first-index ties ----------------
__global__ void __launch_bounds__(256) k_argmin() {
    __shared__ float4 sp[NPT];
    __shared__ float  sg[NPT];
    const int b = blockIdx.y;
    const int base = b * NPT;
    const int tid = threadIdx.x;
    for (int j = tid; j < NPT; j += 256) { sp[j] = g_yp[base + j]; sg[j] = g_g[base + j]; }
    __syncthreads();
    const int warp = tid >> 5, lane = tid & 31;
    const int r0 = blockIdx.x * 32 + warp * 4;

    float qx[4], qy[4], qz[4], qn[4];
#pragma unroll
    for (int k = 0; k < 4; k++) {
        float4 q = g_xp[base + r0 + k];
        qx[k] = q.x; qy[k] = q.y; qz[k] = q.z; qn[k] = q.w;
    }
    float bv[4] = {INFINITY, INFINITY, INFINITY, INFINITY};
    int   bi[4] = {0, 0, 0, 0};
#pragma unroll 2
    for (int j = lane; j < NPT; j += 32) {
        const float4 p = sp[j];
        const float gg = sg[j];
#pragma unroll
        for (int k = 0; k < 4; k++) {
            float d = fmaf(qz[k], p.z, fmaf(qy[k], p.y, __fmul_rn(qx[k], p.x)));
            float s = fmaf(-2.f, d, __fadd_rn(qn[k], p.w));
            s = fmaxf(s, 0.f);
            float v = __fadd_rn(s, -gg);
            if (v < bv[k]) { bv[k] = v; bi[k] = j; }
        }
    }
#pragma unroll
    for (int k = 0; k < 4; k++) {
#pragma unroll
        for (int o = 16; o; o >>= 1) {
            float v2 = __shfl_xor_sync(0xffffffffu, bv[k], o);
            int   i2 = __shfl_xor_sync(0xffffffffu, bi[k], o);
            if (v2 < bv[k] || (v2 == bv[k] && i2 < bi[k])) { bv[k] = v2; bi[k] = i2; }
        }
    }
    if (lane == 0) {
#pragma unroll
        for (int k = 0; k < 4; k++) g_idx[base + r0 + k] = bi[k];
    }
}

// ---------------- gather + MLP head, write (v_pred, v) ----------------
__global__ void __launch_bounds__(256) k_mlp(const float* __restrict__ noise, const float* __restrict__ tt,
                                             const float* __restrict__ W1, const float* __restrict__ Wt,
                                             const float* __restrict__ b1, const float* __restrict__ W2,
                                             const float* __restrict__ b2, float* __restrict__ out) {
    __shared__ float sW1[3 * HID], sW2[HID * 3], sWt[HID], sb1[HID];
    const int tid = threadIdx.x;
    for (int i = tid; i < 3 * HID; i += 256) { sW1[i] = W1[i]; sW2[i] = W2[i]; }
    for (int i = tid; i < HID; i += 256) { sWt[i] = Wt[i]; sb1[i] = b1[i]; }
    __syncthreads();

    const int p = blockIdx.x * 256 + tid;
    const int b = p >> 11;
    const float t = tt[b];
    const int id = g_idx[p];
    const float4 y = g_yp[(b << 11) + id];
    const float n0 = noise[p * 3 + 0], n1 = noise[p * 3 + 1], n2 = noise[p * 3 + 2];
    const float v0 = __fadd_rn(n0, -y.x);
    const float v1 = __fadd_rn(n1, -y.y);
    const float v2 = __fadd_rn(n2, -y.z);
    const float omt = __fadd_rn(1.f, -t);
    const float x0t = __fadd_rn(__fmul_rn(omt, y.x), __fmul_rn(t, n0));
    const float x1t = __fadd_rn(__fmul_rn(omt, y.y), __fmul_rn(t, n1));
    const float x2t = __fadd_rn(__fmul_rn(omt, y.z), __fmul_rn(t, n2));

    float a0 = b2[0], a1 = b2[1], a2 = b2[2];
#pragma unroll 8
    for (int j = 0; j < HID; j++) {
        float h = fmaf(x2t, sW1[2 * HID + j], fmaf(x1t, sW1[HID + j], __fmul_rn(x0t, sW1[j])));
        h = __fadd_rn(__fadd_rn(h, __fmul_rn(t, sWt[j])), sb1[j]);
        h = fmaxf(h, 0.f);
        a0 = fmaf(h, sW2[j * 3 + 0], a0);
        a1 = fmaf(h, sW2[j * 3 + 1], a1);
        a2 = fmaf(h, sW2[j * 3 + 2], a2);
    }
    out[p * 3 + 0] = a0;
    out[p * 3 + 1] = a1;
    out[p * 3 + 2] = a2;
    out[NTOT * 3 + p * 3 + 0] = v0;
    out[NTOT * 3 + p * 3 + 1] = v1;
    out[NTOT * 3 + p * 3 + 2] = v2;
}

// ---------------- launcher ----------------
extern "C" void kernel_launch(void* const* d_in, const int* in_sizes, int n_in,
                              void* d_out, int out_size) {
    const float* cloud = (const float*)d_in[0];
    const float* noise = (const float*)d_in[1];
    const float* t     = (const float*)d_in[2];
    const float* W1    = (const float*)d_in[3];
    const float* Wt    = (const float*)d_in[4];
    const float* b1    = (const float*)d_in[5];
    const float* W2    = (const float*)d_in[6];
    const float* b2    = (const float*)d_in[7];
    float* out = (float*)d_out;

    k_std<<<BB, 256>>>(cloud);
    k_pack<<<NTOT / 256, 256>>>(cloud, noise);

    // EPS_LIST = np.geomspace(32.0, 0.001**2, 14).astype(np.float32)
    const double blur2 = 0.001 * 0.001;
    const double l0 = log10(32.0);
    const double l1 = log10(blur2);
    const double step = (l1 - l0) / (double)(NITER - 1);
    const double LOG2E = 1.4426950408889634;
    const dim3 gridH(NPT / 16, BB);   // 2 rows/warp, 16 rows/block -> 1024 blocks
    const dim3 gridA(NPT / 32, BB);

    for (int it = 0; it < NITER; it++) {
        double ev;
        if (it == 0)              ev = 32.0;
        else if (it == NITER - 1) ev = blur2;
        else                      ev = pow(10.0, l0 + (double)it * step);
        const float eps = (float)ev;
        const float ie2 = (float)((double)(1.0f / eps) * LOG2E);
        k_half<0><<<gridH, 256>>>(eps, ie2);  // f-update
        k_half<1><<<gridH, 256>>>(eps, ie2);  // g-update
    }

    k_argmin<<<gridA, 256>>>();
    k_mlp<<<NTOT / 256, 256>>>(noise, t, W1, Wt, b1, W2, b2, out);

    (void)in_sizes; (void)n_in; (void)out_size;
}

// round 9
// speedup vs baseline: 1.8700x; 1.3550x over previous
#include <cuda_runtime.h>
#include <math.h>

#define BB  8
#define NPT 2048
#define NTOT (BB*NPT)
#define HID 256
#define NITER 14

typedef unsigned long long u64;

// ---------------- f32x2 packed helpers (sm_103a) ----------------
__device__ __forceinline__ u64 pk2(float lo, float hi) {
    u64 r; asm("mov.b64 %0,{%1,%2};" : "=l"(r) : "f"(lo), "f"(hi)); return r;
}
__device__ __forceinline__ void up2(u64 v, float& lo, float& hi) {
    asm("mov.b64 {%0,%1},%2;" : "=f"(lo), "=f"(hi) : "l"(v));
}
__device__ __forceinline__ u64 fma2_(u64 a, u64 b, u64 c) {
    u64 r; asm("fma.rn.f32x2 %0,%1,%2,%3;" : "=l"(r) : "l"(a), "l"(b), "l"(c)); return r;
}
__device__ __forceinline__ float ex2_(float x) {
    float r; asm("ex2.approx.f32 %0,%1;" : "=f"(r) : "f"(x)); return r;
}

// ---------------- persistent scratch ----------------
__device__ float4 g_xp[NTOT];   // noise points packed: (x,y,z,|x|^2)
__device__ float4 g_yp[NTOT];   // x0 points packed:    (x,y,z,|y|^2)
// interleaved pair tiles for k_half reduce side:
//   g_xy*[pair] = (x_{2j}, x_{2j+1}, y_{2j}, y_{2j+1})
//   g_zc*[pair] = (z_{2j}, z_{2j+1}, c_{2j}, c_{2j+1}),  c = phi - 0.5*|p|^2
__device__ float4 g_xyX[NTOT/2], g_zcX[NTOT/2];   // X side (noise)
__device__ float4 g_xyY[NTOT/2], g_zcY[NTOT/2];   // Y side (x0)
__device__ float  g_g[NTOT];
__device__ float  g_std[BB];
__device__ int    g_idx[NTOT];

// ---------------- per-batch std (ddof=1) ----------------
__global__ void k_std(const float* __restrict__ cloud) {
    __shared__ float red[256];
    const int b = blockIdx.x;
    const float* p = cloud + b * NPT * 3;
    const int tid = threadIdx.x;
    float s = 0.f;
    for (int i = tid; i < NPT * 3; i += 256) s += p[i];
    red[tid] = s; __syncthreads();
    for (int o = 128; o > 0; o >>= 1) { if (tid < o) red[tid] += red[tid + o]; __syncthreads(); }
    const float mean = red[0] / (float)(NPT * 3);
    __syncthreads();
    float s2 = 0.f;
    for (int i = tid; i < NPT * 3; i += 256) { float d = p[i] - mean; s2 = fmaf(d, d, s2); }
    red[tid] = s2; __syncthreads();
    for (int o = 128; o > 0; o >>= 1) { if (tid < o) red[tid] += red[tid + o]; __syncthreads(); }
    if (tid == 0) g_std[b] = sqrtf(red[0] / (float)(NPT * 3 - 1));
}

// ---------------- pack points, build interleaved tiles, init folded constants ----------------
__global__ void k_pack(const float* __restrict__ cloud, const float* __restrict__ noise) {
    int i = blockIdx.x * blockDim.x + threadIdx.x;
    if (i >= NTOT) return;
    int b = i >> 11;
    float sd = g_std[b];
    float c0 = cloud[i * 3 + 0] / sd;
    float c1 = cloud[i * 3 + 1] / sd;
    float c2 = cloud[i * 3 + 2] / sd;
    float yn = __fadd_rn(__fadd_rn(__fmul_rn(c0, c0), __fmul_rn(c1, c1)), __fmul_rn(c2, c2));
    g_yp[i] = make_float4(c0, c1, c2, yn);
    float n0 = noise[i * 3 + 0], n1 = noise[i * 3 + 1], n2 = noise[i * 3 + 2];
    float xn = __fadd_rn(__fadd_rn(__fmul_rn(n0, n0), __fmul_rn(n1, n1)), __fmul_rn(n2, n2));
    g_xp[i] = make_float4(n0, n1, n2, xn);

    const int pr = i >> 1, h = i & 1;
    float* fxyX = (float*)g_xyX; float* fzcX = (float*)g_zcX;
    float* fxyY = (float*)g_xyY; float* fzcY = (float*)g_zcY;
    fxyX[pr * 4 + h]     = n0;
    fxyX[pr * 4 + 2 + h] = n1;
    fzcX[pr * 4 + h]     = n2;
    fzcX[pr * 4 + 2 + h] = __fmul_rn(-0.5f, xn);   // phi==0 -> c = -0.5|x|^2
    fxyY[pr * 4 + h]     = c0;
    fxyY[pr * 4 + 2 + h] = c1;
    fzcY[pr * 4 + h]     = c2;
    fzcY[pr * 4 + 2 + h] = __fmul_rn(-0.5f, yn);
}

// log2(1/2048) is exactly -11
#define LOGC2 (-11.0f)
#define LN2F  (0.6931471805599453f)
#define ARG_HI 96.0f
#define ARG_LO (-80.0f)

// ---------------- one Sinkhorn half-update: SINGLE PASS with duality-based shift ----------------
// arg(i,j) = (q_i.p_j + c_j)*ie2 + khat_i,  khat_i = c_row_i * ie2  (M-hat = -c_row_i).
// Sinkhorn duality: true max arg in [0, ln2048*eps_prev*ie2] + drift -> almost always in
// [ARG_LO, ARG_HI]. True max tracked in-loop (ALU); warp-uniform fallback re-runs with
// exact shift if out of window. Result is algebraically exact for ANY shift.
// DIR==0: q/rows = noise(x), tile = x0(y) -> writes cX; DIR==1: rows = x0(y), tile = noise(x) -> g, cY
template <int DIR>
__global__ void __launch_bounds__(256, 4) k_half(float eps, float ie2 /* (1/eps)*log2(e) */) {
    __shared__ __align__(16) ulonglong2 sXY[NPT/2], sZC[NPT/2];
    const int b = blockIdx.y;
    const int base = b * NPT;
    const float4* __restrict__ vxy = (DIR ? g_xyX : g_xyY) + (base >> 1);
    const float4* __restrict__ vzc = (DIR ? g_zcX : g_zcY) + (base >> 1);
    const float4* __restrict__ Pq  = DIR ? g_yp : g_xp;
    const float*  __restrict__ rowzc = (const float*)(DIR ? g_zcY : g_zcX);

    const int tid = threadIdx.x;
    {
        float4* dxy = (float4*)sXY; float4* dzc = (float4*)sZC;
#pragma unroll
        for (int j = tid; j < NPT / 2; j += 256) { dxy[j] = vxy[j]; dzc[j] = vzc[j]; }
    }
    __syncthreads();

    const int warp = tid >> 5, lane = tid & 31;
    const int r0 = blockIdx.x * 32 + warp * 4;

    u64 qx2[4], qy2[4], qz2[4], K[4];
    float qw[4], khat[4];
#pragma unroll
    for (int k = 0; k < 4; k++) {
        float4 q = Pq[base + r0 + k];
        qx2[k] = pk2(q.x, q.x);
        qy2[k] = pk2(q.y, q.y);
        qz2[k] = pk2(q.z, q.z);
        qw[k] = q.w;
        // own row's folded constant: c_row = phi_row - 0.5|q|^2 ; shift khat = c_row*ie2
        float crow = rowzc[(((base + r0) >> 1) + (k >> 1)) * 4 + 2 + (k & 1)];
        khat[k] = __fmul_rn(crow, ie2);
        K[k] = pk2(khat[k], khat[k]);
    }
    const u64 IE2P = pk2(ie2, ie2);

    float aL[4] = {0.f, 0.f, 0.f, 0.f};
    float aH[4] = {0.f, 0.f, 0.f, 0.f};
    float mx[4] = {-INFINITY, -INFINITY, -INFINITY, -INFINITY};

#pragma unroll 4
    for (int it = 0; it < NPT / 64; ++it) {
        const int jj = lane + it * 32;
        const ulonglong2 pxy = sXY[jj];
        const ulonglong2 pzc = sZC[jj];
#pragma unroll
        for (int k = 0; k < 4; k++) {
            u64 t  = fma2_(qz2[k], pzc.x, fma2_(qy2[k], pxy.y, fma2_(qx2[k], pxy.x, pzc.y)));
            u64 ea = fma2_(IE2P, t, K[k]);
            float el, eh; up2(ea, el, eh);
            mx[k] = fmaxf(mx[k], fmaxf(el, eh));
            aL[k] += ex2_(el);
            aH[k] += ex2_(eh);
        }
    }

    // warp-reduce the true arg-max per row (all lanes end with identical values)
#pragma unroll
    for (int k = 0; k < 4; k++) {
#pragma unroll
        for (int o = 16; o; o >>= 1) mx[k] = fmaxf(mx[k], __shfl_xor_sync(0xffffffffu, mx[k], o));
    }
    bool ok = true;
#pragma unroll
    for (int k = 0; k < 4; k++) ok = ok && (mx[k] <= ARG_HI) && (mx[k] >= ARG_LO);

    if (!ok) {   // warp-uniform rare path: shift so each row's max arg -> 0, redo
#pragma unroll
        for (int k = 0; k < 4; k++) {
            khat[k] = __fadd_rn(khat[k], -mx[k]);
            K[k] = pk2(khat[k], khat[k]);
            aL[k] = 0.f; aH[k] = 0.f;
        }
#pragma unroll 4
        for (int it = 0; it < NPT / 64; ++it) {
            const int jj = lane + it * 32;
            const ulonglong2 pxy = sXY[jj];
            const ulonglong2 pzc = sZC[jj];
#pragma unroll
            for (int k = 0; k < 4; k++) {
                u64 t  = fma2_(qz2[k], pzc.x, fma2_(qy2[k], pxy.y, fma2_(qx2[k], pxy.x, pzc.y)));
                u64 ea = fma2_(IE2P, t, K[k]);
                float el, eh; up2(ea, el, eh);
                aL[k] += ex2_(el);
                aH[k] += ex2_(eh);
            }
        }
    }

    float sw[4];
#pragma unroll
    for (int k = 0; k < 4; k++) {
        float a = __fadd_rn(aL[k], aH[k]);
#pragma unroll
        for (int o = 16; o; o >>= 1) a += __shfl_xor_sync(0xffffffffu, a, o);
        sw[k] = a;
    }

    if (lane == 0) {
#pragma unroll
        for (int k = 0; k < 4; k++) {
            // ln(sum_j exp(t_j/eps)) = ln S - khat*ln2 ;  fold LOGC2:
            // cnew = phi_new - 0.5|q|^2 = -eps*( (LOGC2 - khat)*ln2 + ln S )
            float base2 = __fadd_rn(LOGC2, -khat[k]);
            float cnew = __fmul_rn(-eps, fmaf(base2, LN2F, logf(sw[k])));
            const int pr4 = (((base + r0) >> 1) + (k >> 1)) * 4 + 2 + (k & 1);
            if (DIR == 0) {
                ((float*)g_zcX)[pr4] = cnew;                     // f - 0.5|x|^2
            } else {
                g_g[base + r0 + k] = fmaf(0.5f, qw[k], cnew);    // g (for argmin)
                ((float*)g_zcY)[pr4] = cnew;                     // g - 0.5|y|^2
            }
        }
    }
}

// ---------------- argmin over m of (sqdist - g_m), first-index ties ----------------
__global__ void __launch_bounds__(256) k_argmin() {
    __shared__ float4 sp[NPT];
    __shared__ float  sg[NPT];
    const int b = blockIdx.y;
    const int base = b * NPT;
    const int tid = threadIdx.x;
    for (int j = tid; j < NPT; j += 256) { sp[j] = g_yp[base + j]; sg[j] = g_g[base + j]; }
    __syncthreads();
    const int warp = tid >> 5, lane = tid & 31;
    const int r0 = blockIdx.x * 32 + warp * 4;

    float qx[4], qy[4], qz[4], qn[4];
#pragma unroll
    for (int k = 0; k < 4; k++) {
        float4 q = g_xp[base + r0 + k];
        qx[k] = q.x; qy[k] = q.y; qz[k] = q.z; qn[k] = q.w;
    }
    float bv[4] = {INFINITY, INFINITY, INFINITY, INFINITY};
    int   bi[4] = {0, 0, 0, 0};
#pragma unroll 2
    for (int j = lane; j < NPT; j += 32) {
        const float4 p = sp[j];
        const float gg = sg[j];
#pragma unroll
        for (int k = 0; k < 4; k++) {
            float d = fmaf(qz[k], p.z, fmaf(qy[k], p.y, __fmul_rn(qx[k], p.x)));
            float s = fmaf(-2.f, d, __fadd_rn(qn[k], p.w));
            s = fmaxf(s, 0.f);
            float v = __fadd_rn(s, -gg);
            if (v < bv[k]) { bv[k] = v; bi[k] = j; }
        }
    }
#pragma unroll
    for (int k = 0; k < 4; k++) {
#pragma unroll
        for (int o = 16; o; o >>= 1) {
            float v2 = __shfl_xor_sync(0xffffffffu, bv[k], o);
            int   i2 = __shfl_xor_sync(0xffffffffu, bi[k], o);
            if (v2 < bv[k] || (v2 == bv[k] && i2 < bi[k])) { bv[k] = v2; bi[k] = i2; }
        }
    }
    if (lane == 0) {
#pragma unroll
        for (int k = 0; k < 4; k++) g_idx[base + r0 + k] = bi[k];
    }
}

// ---------------- gather + MLP head, write (v_pred, v) ----------------
__global__ void __launch_bounds__(256) k_mlp(const float* __restrict__ noise, const float* __restrict__ tt,
                                             const float* __restrict__ W1, const float* __restrict__ Wt,
                                             const float* __restrict__ b1, const float* __restrict__ W2,
                                             const float* __restrict__ b2, float* __restrict__ out) {
    __shared__ float sW1[3 * HID], sW2[HID * 3], sWt[HID], sb1[HID];
    const int tid = threadIdx.x;
    for (int i = tid; i < 3 * HID; i += 256) { sW1[i] = W1[i]; sW2[i] = W2[i]; }
    for (int i = tid; i < HID; i += 256) { sWt[i] = Wt[i]; sb1[i] = b1[i]; }
    __syncthreads();

    const int p = blockIdx.x * 256 + tid;
    const int b = p >> 11;
    const float t = tt[b];
    const int id = g_idx[p];
    const float4 y = g_yp[(b << 11) + id];
    const float n0 = noise[p * 3 + 0], n1 = noise[p * 3 + 1], n2 = noise[p * 3 + 2];
    const float v0 = __fadd_rn(n0, -y.x);
    const float v1 = __fadd_rn(n1, -y.y);
    const float v2 = __fadd_rn(n2, -y.z);
    const float omt = __fadd_rn(1.f, -t);
    const float x0t = __fadd_rn(__fmul_rn(omt, y.x), __fmul_rn(t, n0));
    const float x1t = __fadd_rn(__fmul_rn(omt, y.y), __fmul_rn(t, n1));
    const float x2t = __fadd_rn(__fmul_rn(omt, y.z), __fmul_rn(t, n2));

    float a0 = b2[0], a1 = b2[1], a2 = b2[2];
#pragma unroll 8
    for (int j = 0; j < HID; j++) {
        float h = fmaf(x2t, sW1[2 * HID + j], fmaf(x1t, sW1[HID + j], __fmul_rn(x0t, sW1[j])));
        h = __fadd_rn(__fadd_rn(h, __fmul_rn(t, sWt[j])), sb1[j]);
        h = fmaxf(h, 0.f);
        a0 = fmaf(h, sW2[j * 3 + 0], a0);
        a1 = fmaf(h, sW2[j * 3 + 1], a1);
        a2 = fmaf(h, sW2[j * 3 + 2], a2);
    }
    out[p * 3 + 0] = a0;
    out[p * 3 + 1] = a1;
    out[p * 3 + 2] = a2;
    out[NTOT * 3 + p * 3 + 0] = v0;
    out[NTOT * 3 + p * 3 + 1] = v1;
    out[NTOT * 3 + p * 3 + 2] = v2;
}

// ---------------- launcher ----------------
extern "C" void kernel_launch(void* const* d_in, const int* in_sizes, int n_in,
                              void* d_out, int out_size) {
    const float* cloud = (const float*)d_in[0];
    const float* noise = (const float*)d_in[1];
    const float* t     = (const float*)d_in[2];
    const float* W1    = (const float*)d_in[3];
    const float* Wt    = (const float*)d_in[4];
    const float* b1    = (const float*)d_in[5];
    const float* W2    = (const float*)d_in[6];
    const float* b2    = (const float*)d_in[7];
    float* out = (float*)d_out;

    k_std<<<BB, 256>>>(cloud);
    k_pack<<<NTOT / 256, 256>>>(cloud, noise);

    // EPS_LIST = np.geomspace(32.0, 0.001**2, 14).astype(np.float32)
    const double blur2 = 0.001 * 0.001;
    const double l0 = log10(32.0);
    const double l1 = log10(blur2);
    const double step = (l1 - l0) / (double)(NITER - 1);
    const double LOG2E = 1.4426950408889634;
    const dim3 gridH(NPT / 32, BB);   // 4 rows/warp, 32 rows/block -> 512 blocks
    const dim3 gridA(NPT / 32, BB);

    for (int it = 0; it < NITER; it++) {
        double ev;
        if (it == 0)              ev = 32.0;
        else if (it == NITER - 1) ev = blur2;
        else                      ev = pow(10.0, l0 + (double)it * step);
        const float eps = (float)ev;
        const float ie2 = (float)((double)(1.0f / eps) * LOG2E);
        k_half<0><<<gridH, 256>>>(eps, ie2);  // f-update
        k_half<1><<<gridH, 256>>>(eps, ie2);  // g-update
    }

    k_argmin<<<gridA, 256>>>();
    k_mlp<<<NTOT / 256, 256>>>(noise, t, W1, Wt, b1, W2, b2, out);

    (void)in_sizes; (void)n_in; (void)out_size;
}

// round 10
// speedup vs baseline: 1.8963x; 1.0141x over previous
#include <cuda_runtime.h>
#include <math.h>

#define BB  8
#define NPT 2048
#define NTOT (BB*NPT)
#define HID 256
#define NITER 14

typedef unsigned long long u64;

// ---------------- f32x2 packed helpers (sm_103a) ----------------
__device__ __forceinline__ u64 pk2(float lo, float hi) {
    u64 r; asm("mov.b64 %0,{%1,%2};" : "=l"(r) : "f"(lo), "f"(hi)); return r;
}
__device__ __forceinline__ void up2(u64 v, float& lo, float& hi) {
    asm("mov.b64 {%0,%1},%2;" : "=f"(lo), "=f"(hi) : "l"(v));
}
__device__ __forceinline__ u64 fma2_(u64 a, u64 b, u64 c) {
    u64 r; asm("fma.rn.f32x2 %0,%1,%2,%3;" : "=l"(r) : "l"(a), "l"(b), "l"(c)); return r;
}
__device__ __forceinline__ float ex2_(float x) {
    float r; asm("ex2.approx.f32 %0,%1;" : "=f"(r) : "f"(x)); return r;
}

// ---------------- persistent scratch ----------------
__device__ float4 g_xp[NTOT];   // noise points packed: (x,y,z,|x|^2)
__device__ float4 g_yp[NTOT];   // x0 points packed:    (x,y,z,|y|^2)
// interleaved pair tiles for k_half reduce side:
//   g_xy*[pair] = (x_{2j}, x_{2j+1}, y_{2j}, y_{2j+1})
//   g_zc*[pair] = (z_{2j}, z_{2j+1}, c_{2j}, c_{2j+1}),  c = phi - 0.5*|p|^2
__device__ float4 g_xyX[NTOT/2], g_zcX[NTOT/2];   // X side (noise)
__device__ float4 g_xyY[NTOT/2], g_zcY[NTOT/2];   // Y side (x0)
__device__ float  g_g[NTOT];
__device__ float  g_std[BB];
__device__ int    g_idx[NTOT];
// j-split partial-sum machinery
__device__ float  g_acc[NTOT];     // per-row partial sum accumulator (zero outside launches)
__device__ int    g_cnt[BB * 64];  // per (batch, rowblock) arrival counter

// ---------------- per-batch std (ddof=1) ----------------
__global__ void k_std(const float* __restrict__ cloud) {
    __shared__ float red[256];
    const int b = blockIdx.x;
    const float* p = cloud + b * NPT * 3;
    const int tid = threadIdx.x;
    float s = 0.f;
    for (int i = tid; i < NPT * 3; i += 256) s += p[i];
    red[tid] = s; __syncthreads();
    for (int o = 128; o > 0; o >>= 1) { if (tid < o) red[tid] += red[tid + o]; __syncthreads(); }
    const float mean = red[0] / (float)(NPT * 3);
    __syncthreads();
    float s2 = 0.f;
    for (int i = tid; i < NPT * 3; i += 256) { float d = p[i] - mean; s2 = fmaf(d, d, s2); }
    red[tid] = s2; __syncthreads();
    for (int o = 128; o > 0; o >>= 1) { if (tid < o) red[tid] += red[tid + o]; __syncthreads(); }
    if (tid == 0) g_std[b] = sqrtf(red[0] / (float)(NPT * 3 - 1));
}

// ---------------- pack points, build interleaved tiles, init folded constants ----------------
__global__ void k_pack(const float* __restrict__ cloud, const float* __restrict__ noise) {
    int i = blockIdx.x * blockDim.x + threadIdx.x;
    if (i >= NTOT) return;
    int b = i >> 11;
    float sd = g_std[b];
    float c0 = cloud[i * 3 + 0] / sd;
    float c1 = cloud[i * 3 + 1] / sd;
    float c2 = cloud[i * 3 + 2] / sd;
    float yn = __fadd_rn(__fadd_rn(__fmul_rn(c0, c0), __fmul_rn(c1, c1)), __fmul_rn(c2, c2));
    g_yp[i] = make_float4(c0, c1, c2, yn);
    float n0 = noise[i * 3 + 0], n1 = noise[i * 3 + 1], n2 = noise[i * 3 + 2];
    float xn = __fadd_rn(__fadd_rn(__fmul_rn(n0, n0), __fmul_rn(n1, n1)), __fmul_rn(n2, n2));
    g_xp[i] = make_float4(n0, n1, n2, xn);

    const int pr = i >> 1, h = i & 1;
    float* fxyX = (float*)g_xyX; float* fzcX = (float*)g_zcX;
    float* fxyY = (float*)g_xyY; float* fzcY = (float*)g_zcY;
    fxyX[pr * 4 + h]     = n0;
    fxyX[pr * 4 + 2 + h] = n1;
    fzcX[pr * 4 + h]     = n2;
    fzcX[pr * 4 + 2 + h] = __fmul_rn(-0.5f, xn);   // phi==0 -> c = -0.5|x|^2
    fxyY[pr * 4 + h]     = c0;
    fxyY[pr * 4 + 2 + h] = c1;
    fzcY[pr * 4 + h]     = c2;
    fzcY[pr * 4 + 2 + h] = __fmul_rn(-0.5f, yn);

    g_acc[i] = 0.f;
    if (i < BB * 64) g_cnt[i] = 0;
}

// log2(1/2048) is exactly -11
#define LOGC2 (-11.0f)
#define LN2F  (0.6931471805599453f)

// ---------------- one Sinkhorn half-update: single pass, duality shift, j-split x2 ----------------
// arg(i,j) = (q_i.p_j + c_j)*ie2 + khat_i,  khat_i = c_row_i*ie2. Duality bounds |arg| <= 83 bits
// (< fp32 overflow at 117), so no max pass and no fallback are needed.
// Grid: blockIdx.x = rowblock*2 + jhalf (128), blockIdx.y = batch. Each block sums its half of j;
// partial sums combine via atomicAdd; second-arriving block finalizes (deterministic: 2-float add).
// DIR==0: rows = noise(x), tile = x0(y) -> writes cX; DIR==1: rows = x0(y), tile = noise(x) -> g, cY
template <int DIR>
__global__ void __launch_bounds__(256, 5) k_half(float eps, float ie2 /* (1/eps)*log2(e) */) {
    __shared__ __align__(16) ulonglong2 sXY[NPT/4], sZC[NPT/4];
    __shared__ int sWin;
    const int b = blockIdx.y;
    const int base = b * NPT;
    const int rowblock = blockIdx.x >> 1;
    const int jhalf = blockIdx.x & 1;
    const float4* __restrict__ vxy = (DIR ? g_xyX : g_xyY) + (base >> 1) + jhalf * (NPT / 4);
    const float4* __restrict__ vzc = (DIR ? g_zcX : g_zcY) + (base >> 1) + jhalf * (NPT / 4);
    const float4* __restrict__ Pq  = DIR ? g_yp : g_xp;
    const float*  __restrict__ rowzc = (const float*)(DIR ? g_zcY : g_zcX);

    const int tid = threadIdx.x;
    {
        float4* dxy = (float4*)sXY; float4* dzc = (float4*)sZC;
#pragma unroll
        for (int j = tid; j < NPT / 4; j += 256) { dxy[j] = vxy[j]; dzc[j] = vzc[j]; }
    }
    __syncthreads();

    const int warp = tid >> 5, lane = tid & 31;
    const int r0 = rowblock * 32 + warp * 4;

    u64 qx2[4], qy2[4], qz2[4], K[4];
#pragma unroll
    for (int k = 0; k < 4; k++) {
        float4 q = Pq[base + r0 + k];
        qx2[k] = pk2(q.x, q.x);
        qy2[k] = pk2(q.y, q.y);
        qz2[k] = pk2(q.z, q.z);
        float crow = rowzc[(((base + r0) >> 1) + (k >> 1)) * 4 + 2 + (k & 1)];
        float khat = __fmul_rn(crow, ie2);
        K[k] = pk2(khat, khat);
    }
    const u64 IE2P = pk2(ie2, ie2);

    float aL[4] = {0.f, 0.f, 0.f, 0.f};
    float aH[4] = {0.f, 0.f, 0.f, 0.f};

#pragma unroll 4
    for (int it = 0; it < NPT / 128; ++it) {
        const int jj = lane + it * 32;
        const ulonglong2 pxy = sXY[jj];
        const ulonglong2 pzc = sZC[jj];
#pragma unroll
        for (int k = 0; k < 4; k++) {
            u64 t  = fma2_(qz2[k], pzc.x, fma2_(qy2[k], pxy.y, fma2_(qx2[k], pxy.x, pzc.y)));
            u64 ea = fma2_(IE2P, t, K[k]);
            float el, eh; up2(ea, el, eh);
            aL[k] += ex2_(el);
            aH[k] += ex2_(eh);
        }
    }

#pragma unroll
    for (int k = 0; k < 4; k++) {
        float a = __fadd_rn(aL[k], aH[k]);
#pragma unroll
        for (int o = 16; o; o >>= 1) a += __shfl_xor_sync(0xffffffffu, a, o);
        if (lane == 0) atomicAdd(&g_acc[base + r0 + k], a);
    }

    __syncthreads();
    if (tid == 0) {
        __threadfence();
        int o = atomicAdd(&g_cnt[b * 64 + rowblock], 1);
        sWin = (o == 1);
    }
    __syncthreads();

    if (sWin && warp == 0) {
        __threadfence();   // acquire: sibling's partial adds visible
        const int row = base + rowblock * 32 + lane;
        float S = g_acc[row];
        g_acc[row] = 0.f;
        const int pr4 = (row >> 1) * 4 + 2 + (row & 1);
        float crow = rowzc[pr4];
        float khat = __fmul_rn(crow, ie2);
        float base2 = __fadd_rn(LOGC2, -khat);
        float cnew = __fmul_rn(-eps, fmaf(base2, LN2F, logf(S)));
        if (DIR == 0) {
            ((float*)g_zcX)[pr4] = cnew;                        // f - 0.5|x|^2
        } else {
            g_g[row] = fmaf(0.5f, g_yp[row].w, cnew);           // g (for argmin)
            ((float*)g_zcY)[pr4] = cnew;                        // g - 0.5|y|^2
        }
        if (lane == 0) g_cnt[b * 64 + rowblock] = 0;
    }
}

// ---------------- argmin over m of (sqdist - g_m), first-index ties ----------------
__global__ void __launch_bounds__(256) k_argmin() {
    __shared__ float4 sp[NPT];
    __shared__ float  sg[NPT];
    const int b = blockIdx.y;
    const int base = b * NPT;
    const int tid = threadIdx.x;
    for (int j = tid; j < NPT; j += 256) { sp[j] = g_yp[base + j]; sg[j] = g_g[base + j]; }
    __syncthreads();
    const int warp = tid >> 5, lane = tid & 31;
    const int r0 = blockIdx.x * 32 + warp * 4;

    float qx[4], qy[4], qz[4], qn[4];
#pragma unroll
    for (int k = 0; k < 4; k++) {
        float4 q = g_xp[base + r0 + k];
        qx[k] = q.x; qy[k] = q.y; qz[k] = q.z; qn[k] = q.w;
    }
    float bv[4] = {INFINITY, INFINITY, INFINITY, INFINITY};
    int   bi[4] = {0, 0, 0, 0};
#pragma unroll 2
    for (int j = lane; j < NPT; j += 32) {
        const float4 p = sp[j];
        const float gg = sg[j];
#pragma unroll
        for (int k = 0; k < 4; k++) {
            float d = fmaf(qz[k], p.z, fmaf(qy[k], p.y, __fmul_rn(qx[k], p.x)));
            float s = fmaf(-2.f, d, __fadd_rn(qn[k], p.w));
            s = fmaxf(s, 0.f);
            float v = __fadd_rn(s, -gg);
            if (v < bv[k]) { bv[k] = v; bi[k] = j; }
        }
    }
#pragma unroll
    for (int k = 0; k < 4; k++) {
#pragma unroll
        for (int o = 16; o; o >>= 1) {
            float v2 = __shfl_xor_sync(0xffffffffu, bv[k], o);
            int   i2 = __shfl_xor_sync(0xffffffffu, bi[k], o);
            if (v2 < bv[k] || (v2 == bv[k] && i2 < bi[k])) { bv[k] = v2; bi[k] = i2; }
        }
    }
    if (lane == 0) {
#pragma unroll
        for (int k = 0; k < 4; k++) g_idx[base + r0 + k] = bi[k];
    }
}

// ---------------- gather + MLP head, write (v_pred, v) ----------------
__global__ void __launch_bounds__(256) k_mlp(const float* __restrict__ noise, const float* __restrict__ tt,
                                             const float* __restrict__ W1, const float* __restrict__ Wt,
                                             const float* __restrict__ b1, const float* __restrict__ W2,
                                             const float* __restrict__ b2, float* __restrict__ out) {
    __shared__ float sW1[3 * HID], sW2[HID * 3], sWt[HID], sb1[HID];
    const int tid = threadIdx.x;
    for (int i = tid; i < 3 * HID; i += 256) { sW1[i] = W1[i]; sW2[i] = W2[i]; }
    for (int i = tid; i < HID; i += 256) { sWt[i] = Wt[i]; sb1[i] = b1[i]; }
    __syncthreads();

    const int p = blockIdx.x * 256 + tid;
    const int b = p >> 11;
    const float t = tt[b];
    const int id = g_idx[p];
    const float4 y = g_yp[(b << 11) + id];
    const float n0 = noise[p * 3 + 0], n1 = noise[p * 3 + 1], n2 = noise[p * 3 + 2];
    const float v0 = __fadd_rn(n0, -y.x);
    const float v1 = __fadd_rn(n1, -y.y);
    const float v2 = __fadd_rn(n2, -y.z);
    const float omt = __fadd_rn(1.f, -t);
    const float x0t = __fadd_rn(__fmul_rn(omt, y.x), __fmul_rn(t, n0));
    const float x1t = __fadd_rn(__fmul_rn(omt, y.y), __fmul_rn(t, n1));
    const float x2t = __fadd_rn(__fmul_rn(omt, y.z), __fmul_rn(t, n2));

    float a0 = b2[0], a1 = b2[1], a2 = b2[2];
#pragma unroll 8
    for (int j = 0; j < HID; j++) {
        float h = fmaf(x2t, sW1[2 * HID + j], fmaf(x1t, sW1[HID + j], __fmul_rn(x0t, sW1[j])));
        h = __fadd_rn(__fadd_rn(h, __fmul_rn(t, sWt[j])), sb1[j]);
        h = fmaxf(h, 0.f);
        a0 = fmaf(h, sW2[j * 3 + 0], a0);
        a1 = fmaf(h, sW2[j * 3 + 1], a1);
        a2 = fmaf(h, sW2[j * 3 + 2], a2);
    }
    out[p * 3 + 0] = a0;
    out[p * 3 + 1] = a1;
    out[p * 3 + 2] = a2;
    out[NTOT * 3 + p * 3 + 0] = v0;
    out[NTOT * 3 + p * 3 + 1] = v1;
    out[NTOT * 3 + p * 3 + 2] = v2;
}

// ---------------- launcher ----------------
extern "C" void kernel_launch(void* const* d_in, const int* in_sizes, int n_in,
                              void* d_out, int out_size) {
    const float* cloud = (const float*)d_in[0];
    const float* noise = (const float*)d_in[1];
    const float* t     = (const float*)d_in[2];
    const float* W1    = (const float*)d_in[3];
    const float* Wt    = (const float*)d_in[4];
    const float* b1    = (const float*)d_in[5];
    const float* W2    = (const float*)d_in[6];
    const float* b2    = (const float*)d_in[7];
    float* out = (float*)d_out;

    k_std<<<BB, 256>>>(cloud);
    k_pack<<<NTOT / 256, 256>>>(cloud, noise);

    // EPS_LIST = np.geomspace(32.0, 0.001**2, 14).astype(np.float32)
    const double blur2 = 0.001 * 0.001;
    const double l0 = log10(32.0);
    const double l1 = log10(blur2);
    const double step = (l1 - l0) / (double)(NITER - 1);
    const double LOG2E = 1.4426950408889634;
    const dim3 gridH((NPT / 32) * 2, BB);   // rowblocks x 2 j-halves -> 1024 blocks
    const dim3 gridA(NPT / 32, BB);

    for (int it = 0; it < NITER; it++) {
        double ev;
        if (it == 0)              ev = 32.0;
        else if (it == NITER - 1) ev = blur2;
        else                      ev = pow(10.0, l0 + (double)it * step);
        const float eps = (float)ev;
        const float ie2 = (float)((double)(1.0f / eps) * LOG2E);
        k_half<0><<<gridH, 256>>>(eps, ie2);  // f-update
        k_half<1><<<gridH, 256>>>(eps, ie2);  // g-update
    }

    k_argmin<<<gridA, 256>>>();
    k_mlp<<<NTOT / 256, 256>>>(noise, t, W1, Wt, b1, W2, b2, out);

    (void)in_sizes; (void)n_in; (void)out_size;
}